// round 4
// baseline (speedup 1.0000x reference)
#include <cuda_runtime.h>
#include <math.h>
#include <stdint.h>

// Problem constants
#define BB    64
#define TT    128
#define INW   128
#define HHD   512
#define NND   2048
#define WWD   64
#define OUTW  128
#define RRD   4
#define CTRL  384            // IN + R*W
#define KGATE 896            // CTRL + H
#define JGATE 2048           // 4*H
#define JOK   448            // OUT + (R+1)*W
#define EPSF  1e-8f

// ------------------------- persistent device state -------------------------
__device__ float g_h[BB * HHD];
__device__ float g_c[BB * HHD];
__device__ float g_M[BB * NND * WWD];          // 33.5 MB
__device__ float g_usage[BB * NND];
__device__ float g_rw[2][BB * RRD * NND];      // ping-pong read weights
__device__ float g_read_vec[BB * RRD * WWD];
__device__ float g_gates[BB * JGATE];          // atomic accumulator, self-zeroing
__device__ float g_okbuf[BB * JOK];            // atomic accumulator, self-zeroing
__device__ float g_sim[BB * RRD * NND];
__device__ float g_Kn[BB * RRD * WWD];         // normalized read keys
__device__ float g_wkey[BB * WWD];             // write key
__device__ int   g_lu[BB];                     // argmin(usage) per batch

// ------------------------------- reset -------------------------------------
__global__ void k_reset() {
    long idx = (long)blockIdx.x * blockDim.x + threadIdx.x;
    if (idx < (long)BB * NND * WWD) g_M[idx] = 1e-6f;
    if (idx < BB * HHD) { g_h[idx] = 0.f; g_c[idx] = 0.f; }
    if (idx < BB * NND) g_usage[idx] = 0.f;
    if (idx < BB * RRD * NND) { g_rw[0][idx] = 0.f; g_rw[1][idx] = 0.f; g_sim[idx] = 0.f; }
    if (idx < BB * RRD * WWD) { g_read_vec[idx] = 0.f; g_Kn[idx] = 0.f; }
    if (idx < BB * JGATE) g_gates[idx] = 0.f;
    if (idx < BB * JOK)   g_okbuf[idx] = 0.f;
    if (idx < BB * WWD)   g_wkey[idx] = 0.f;
    if (idx < BB)         g_lu[idx] = 0;
}

// ------------------------------- GEMM ---------------------------------------
// C[b][j] += sum_k X[b][k] * W[j][k]
// MODE 0: gates.  X = [x_t | read_vec | h] (K=896), W = [Wih | Whh], J=2048,
//         grid (32 jblocks, 7 ksplits), each ksplit covers 128 k (2 tiles of 64).
// MODE 1: out+keys. X = h (K=512), W = [Wout ; Wkey], J=448,
//         grid (7 jblocks, 8 ksplits), each ksplit covers 64 k (1 tile).
// Block: 256 threads. hq = tid&15 spans 16 j, bq = tid>>4 spans 16 b-quads.
// Thread computes 4 j (stride 16) x 4 b (consecutive). x loads are warp-
// broadcast; w tile padded to 17 float4/row -> conflict-free.
template <int MODE>
__global__ void __launch_bounds__(256) k_gemm(
    const float* __restrict__ xt,
    const float* __restrict__ Wih, const float* __restrict__ Whh,
    const float* __restrict__ Wout, const float* __restrict__ Wkey)
{
    __shared__ __align__(16) float4 xs4[BB * 16];   // [b][kk4], KT=64
    __shared__ __align__(16) float4 ws4[64 * 17];   // [r][kk4], padded

    const int tid = threadIdx.x;
    const int hq  = tid & 15;
    const int bq  = tid >> 4;
    const int j0  = blockIdx.x * 64;
    const int ks  = blockIdx.y;
    const int ntiles = (MODE == 0) ? 2 : 1;
    const int kbase  = (MODE == 0) ? ks * 128 : ks * 64;
    const int J      = (MODE == 0) ? JGATE : JOK;
    float* C = (MODE == 0) ? g_gates : g_okbuf;

    float acc[4][4];
#pragma unroll
    for (int g = 0; g < 4; ++g)
#pragma unroll
        for (int i = 0; i < 4; ++i) acc[g][i] = 0.f;

    for (int tile = 0; tile < ntiles; ++tile) {
        const int k0 = kbase + tile * 64;
        // stage X tile (64 b x 64 k)
#pragma unroll
        for (int li = 0; li < 4; ++li) {
            int fid = tid + 256 * li;
            int b = fid >> 4, kk4 = fid & 15;
            int k = k0 + kk4 * 4;
            const float* src;
            if (MODE == 0) {
                if (k < INW)       src = xt + b * INW + k;
                else if (k < CTRL) src = g_read_vec + b * (RRD * WWD) + (k - INW);
                else               src = g_h + b * HHD + (k - CTRL);
            } else {
                src = g_h + b * HHD + k;
            }
            xs4[fid] = *reinterpret_cast<const float4*>(src);
        }
        // stage W tile (64 j x 64 k)
#pragma unroll
        for (int li = 0; li < 4; ++li) {
            int fid = tid + 256 * li;
            int r = fid >> 4, kk4 = fid & 15;
            int k = k0 + kk4 * 4;
            int j = j0 + r;
            const float* src;
            if (MODE == 0) {
                if (k < CTRL) src = Wih + (size_t)j * CTRL + k;
                else          src = Whh + (size_t)j * HHD + (k - CTRL);
            } else {
                if (j < OUTW) src = Wout + (size_t)j * HHD + k;
                else          src = Wkey + (size_t)(j - OUTW) * HHD + k;
            }
            ws4[r * 17 + kk4] = *reinterpret_cast<const float4*>(src);
        }
        __syncthreads();
#pragma unroll
        for (int kk = 0; kk < 16; ++kk) {
            float4 xv[4], wv[4];
#pragma unroll
            for (int i = 0; i < 4; ++i) xv[i] = xs4[(bq * 4 + i) * 16 + kk];
#pragma unroll
            for (int g = 0; g < 4; ++g) wv[g] = ws4[(g * 16 + hq) * 17 + kk];
#pragma unroll
            for (int g = 0; g < 4; ++g)
#pragma unroll
                for (int i = 0; i < 4; ++i)
                    acc[g][i] += xv[i].x * wv[g].x + xv[i].y * wv[g].y +
                                 xv[i].z * wv[g].z + xv[i].w * wv[g].w;
        }
        __syncthreads();
    }
#pragma unroll
    for (int g = 0; g < 4; ++g)
#pragma unroll
        for (int i = 0; i < 4; ++i)
            atomicAdd(&C[(size_t)(bq * 4 + i) * J + j0 + g * 16 + hq], acc[g][i]);
}

// ------------------------------ LSTM pointwise ------------------------------
__device__ __forceinline__ float sigm(float x) { return 1.f / (1.f + expf(-x)); }

__global__ void k_lstm(const float* __restrict__ bih, const float* __restrict__ bhh) {
    const int b = blockIdx.x;
    const int hh = threadIdx.x;  // 512
    float* gp = g_gates + (size_t)b * JGATE;
    float gi = gp[hh]            + bih[hh]            + bhh[hh];
    float gf = gp[512 + hh]      + bih[512 + hh]      + bhh[512 + hh];
    float gg = gp[1024 + hh]     + bih[1024 + hh]     + bhh[1024 + hh];
    float go = gp[1536 + hh]     + bih[1536 + hh]     + bhh[1536 + hh];
    gp[hh] = 0.f; gp[512 + hh] = 0.f; gp[1024 + hh] = 0.f; gp[1536 + hh] = 0.f;
    float c = g_c[b * HHD + hh];
    float cn = sigm(gf) * c + sigm(gi) * tanhf(gg);
    float hn = sigm(go) * tanhf(cn);
    g_c[b * HHD + hh] = cn;
    g_h[b * HHD + hh] = hn;
}

// --------------------------- per-batch finalize ------------------------------
// writes out[t], normalizes read keys, extracts write key,
// computes argmin(usage) (first-index tie rule), zeroes scratch buffers.
__global__ void k_finish(const float* __restrict__ bout, const float* __restrict__ bkey,
                         float* __restrict__ out, int t) {
    const int b = blockIdx.x;
    const int tid = threadIdx.x;  // 256
    const int wid = tid >> 5, lane = tid & 31;

    if (tid < OUTW)
        out[(size_t)t * BB * OUTW + (size_t)b * OUTW + tid] =
            g_okbuf[(size_t)b * JOK + tid] + bout[tid];

    if (wid < 5) {
        float v0 = g_okbuf[(size_t)b * JOK + OUTW + wid * 64 + lane]      + bkey[wid * 64 + lane];
        float v1 = g_okbuf[(size_t)b * JOK + OUTW + wid * 64 + lane + 32] + bkey[wid * 64 + lane + 32];
        if (wid == 4) {
            g_wkey[b * WWD + lane]      = v0;
            g_wkey[b * WWD + lane + 32] = v1;
        } else {
            float ss = v0 * v0 + v1 * v1;
#pragma unroll
            for (int o = 16; o; o >>= 1) ss += __shfl_xor_sync(0xffffffffu, ss, o);
            float inv = 1.f / (sqrtf(ss) + EPSF);
            g_Kn[b * RRD * WWD + wid * 64 + lane]      = v0 * inv;
            g_Kn[b * RRD * WWD + wid * 64 + lane + 32] = v1 * inv;
        }
    }

    // argmin over usage[b][:]
    __shared__ float sv[256];
    __shared__ int   si[256];
    float bv = 3.4e38f; int bi = 0;
    for (int i = tid; i < NND; i += 256) {
        float u = g_usage[b * NND + i];
        if (u < bv) { bv = u; bi = i; }
    }
    sv[tid] = bv; si[tid] = bi;
    __syncthreads();
    for (int s = 128; s; s >>= 1) {
        if (tid < s) {
            float ov = sv[tid + s]; int oi = si[tid + s];
            if (ov < sv[tid] || (ov == sv[tid] && oi < si[tid])) { sv[tid] = ov; si[tid] = oi; }
        }
        __syncthreads();
    }
    if (tid == 0) g_lu[b] = si[0];

    // all reads above are complete (the argmin tree synced); zero scratch
    for (int i = tid; i < RRD * WWD; i += 256) g_read_vec[b * RRD * WWD + i] = 0.f;
    for (int i = tid; i < JOK; i += 256)       g_okbuf[(size_t)b * JOK + i] = 0.f;
}

// --------------------------------- sim --------------------------------------
// sim[b][r][n] = (Kn[b][r] . M[b][n]) / (||M[b][n]|| + eps)
__global__ void __launch_bounds__(256) k_sim() {
    const int b   = blockIdx.y;
    const int nb  = blockIdx.x;       // 32 blocks x 64 n
    const int tid = threadIdx.x, wid = tid >> 5, lane = tid & 31;
    __shared__ __align__(16) float kn[RRD * WWD];
    if (tid < RRD * WWD) kn[tid] = g_Kn[b * RRD * WWD + tid];
    __syncthreads();
    const float2 k0 = ((const float2*)kn)[0 * 32 + lane];
    const float2 k1 = ((const float2*)kn)[1 * 32 + lane];
    const float2 k2 = ((const float2*)kn)[2 * 32 + lane];
    const float2 k3 = ((const float2*)kn)[3 * 32 + lane];
#pragma unroll
    for (int i = 0; i < 8; ++i) {
        int n = nb * 64 + wid * 8 + i;
        float2 m = ((const float2*)(g_M + (size_t)(b * NND + n) * WWD))[lane];
        float ss = m.x * m.x + m.y * m.y;
        float d0 = m.x * k0.x + m.y * k0.y;
        float d1 = m.x * k1.x + m.y * k1.y;
        float d2 = m.x * k2.x + m.y * k2.y;
        float d3 = m.x * k3.x + m.y * k3.y;
#pragma unroll
        for (int o = 16; o; o >>= 1) {
            ss += __shfl_xor_sync(0xffffffffu, ss, o);
            d0 += __shfl_xor_sync(0xffffffffu, d0, o);
            d1 += __shfl_xor_sync(0xffffffffu, d1, o);
            d2 += __shfl_xor_sync(0xffffffffu, d2, o);
            d3 += __shfl_xor_sync(0xffffffffu, d3, o);
        }
        if (lane == 0) {
            float inv = 1.f / (sqrtf(ss) + EPSF);
            g_sim[(size_t)(b * RRD + 0) * NND + n] = d0 * inv;
            g_sim[(size_t)(b * RRD + 1) * NND + n] = d1 * inv;
            g_sim[(size_t)(b * RRD + 2) * NND + n] = d2 * inv;
            g_sim[(size_t)(b * RRD + 3) * NND + n] = d3 * inv;
        }
    }
}

// -------------------------------- softmax -----------------------------------
__global__ void k_softmax(int sel) {
    const int br  = blockIdx.x;       // b*4 + r
    const int tid = threadIdx.x;      // 256
    float* __restrict__ rw_new = g_rw[sel];
    const float* s = g_sim + (size_t)br * NND;
    float v[8];
    float m = -3.4e38f;
#pragma unroll
    for (int j = 0; j < 8; ++j) { v[j] = s[tid + 256 * j]; m = fmaxf(m, v[j]); }
    __shared__ float red[256];
    red[tid] = m; __syncthreads();
    for (int st = 128; st; st >>= 1) { if (tid < st) red[tid] = fmaxf(red[tid], red[tid + st]); __syncthreads(); }
    m = red[0];
    __syncthreads();
    float sum = 0.f;
#pragma unroll
    for (int j = 0; j < 8; ++j) { v[j] = expf(v[j] - m); sum += v[j]; }
    red[tid] = sum; __syncthreads();
    for (int st = 128; st; st >>= 1) { if (tid < st) red[tid] += red[tid + st]; __syncthreads(); }
    float inv = 1.f / red[0];
#pragma unroll
    for (int j = 0; j < 8; ++j)
        rw_new[(size_t)br * NND + tid + 256 * j] = v[j] * inv;
}

// ------------------------------ memory update --------------------------------
// single pass over M: compute read_vec (old M), write M_new, update usage.
__global__ void __launch_bounds__(256) k_update(int sel,
                                                const float* __restrict__ alpha,
                                                const float* __restrict__ gamma) {
    const int b   = blockIdx.y;
    const int cx  = blockIdx.x;       // 16 chunks x 128 n
    const int tid = threadIdx.x, wid = tid >> 5, lane = tid & 31;
    const float* __restrict__ rw_new = g_rw[sel];
    const float* __restrict__ rw_old = g_rw[sel ^ 1];
    const float sa = 1.f / (1.f + expf(-alpha[0]));
    const float gm = gamma[0];
    const int lu = g_lu[b];

    __shared__ __align__(16) float wk[WWD];
    if (tid < WWD) wk[tid] = g_wkey[b * WWD + tid];
    __syncthreads();
    const float2 wk2 = ((const float2*)wk)[lane];

    float2 a0 = {0.f, 0.f}, a1 = {0.f, 0.f}, a2 = {0.f, 0.f}, a3 = {0.f, 0.f};
#pragma unroll 4
    for (int i = 0; i < 16; ++i) {
        int n = cx * 128 + wid * 16 + i;
        size_t moff = (size_t)(b * NND + n) * WWD;
        float2 m = ((const float2*)(g_M + moff))[lane];
        float r0o = rw_old[(size_t)(b * RRD + 0) * NND + n];
        float r1o = rw_old[(size_t)(b * RRD + 1) * NND + n];
        float r2o = rw_old[(size_t)(b * RRD + 2) * NND + n];
        float r3o = rw_old[(size_t)(b * RRD + 3) * NND + n];
        float r0 = rw_new[(size_t)(b * RRD + 0) * NND + n];
        float r1 = rw_new[(size_t)(b * RRD + 1) * NND + n];
        float r2 = rw_new[(size_t)(b * RRD + 2) * NND + n];
        float r3 = rw_new[(size_t)(b * RRD + 3) * NND + n];
        float so = r0o + r1o + r2o + r3o;
        bool is_lu = (n == lu);
        float ww = sa * so + (is_lu ? (1.f - sa) : 0.f);
        float2 mn;
        mn.x = (is_lu ? 0.f : m.x) + ww * wk2.x;
        mn.y = (is_lu ? 0.f : m.y) + ww * wk2.y;
        ((float2*)(g_M + moff))[lane] = mn;
        // read_vec uses OLD M
        a0.x += r0 * m.x; a0.y += r0 * m.y;
        a1.x += r1 * m.x; a1.y += r1 * m.y;
        a2.x += r2 * m.x; a2.y += r2 * m.y;
        a3.x += r3 * m.x; a3.y += r3 * m.y;
        if (lane == 0)
            g_usage[b * NND + n] = gm * g_usage[b * NND + n] + (r0 + r1 + r2 + r3) + ww;
    }
    // cross-warp reduce into read_vec
    __shared__ float red[8][RRD * WWD];
    float* rp = red[wid];
    rp[0 * WWD + 2 * lane] = a0.x; rp[0 * WWD + 2 * lane + 1] = a0.y;
    rp[1 * WWD + 2 * lane] = a1.x; rp[1 * WWD + 2 * lane + 1] = a1.y;
    rp[2 * WWD + 2 * lane] = a2.x; rp[2 * WWD + 2 * lane + 1] = a2.y;
    rp[3 * WWD + 2 * lane] = a3.x; rp[3 * WWD + 2 * lane + 1] = a3.y;
    __syncthreads();
    if (tid < RRD * WWD) {
        float s = 0.f;
#pragma unroll
        for (int w = 0; w < 8; ++w) s += red[w][tid];
        atomicAdd(&g_read_vec[b * RRD * WWD + tid], s);
    }
}

// ------------------------------- launcher ------------------------------------
extern "C" void kernel_launch(void* const* d_in, const int* in_sizes, int n_in,
                              void* d_out, int out_size) {
    const float* x_seq = (const float*)d_in[0];
    const float* Wih   = (const float*)d_in[1];
    const float* Whh   = (const float*)d_in[2];
    const float* bih   = (const float*)d_in[3];
    const float* bhh   = (const float*)d_in[4];
    const float* Wout  = (const float*)d_in[5];
    const float* bout  = (const float*)d_in[6];
    const float* Wkey  = (const float*)d_in[7];
    const float* bkey  = (const float*)d_in[8];
    const float* alpha = (const float*)d_in[9];
    const float* gamma = (const float*)d_in[10];
    float* out = (float*)d_out;

    k_reset<<<32768, 256>>>();

    for (int t = 0; t < TT; ++t) {
        k_gemm<0><<<dim3(32, 7), 256>>>(x_seq + (size_t)t * BB * INW, Wih, Whh, Wout, Wkey);
        k_lstm<<<BB, HHD>>>(bih, bhh);
        k_gemm<1><<<dim3(7, 8), 256>>>(nullptr, Wih, Whh, Wout, Wkey);
        k_finish<<<BB, 256>>>(bout, bkey, out, t);
        k_sim<<<dim3(32, BB), 256>>>();
        k_softmax<<<BB * RRD, 256>>>(t & 1);
        k_update<<<dim3(16, BB), 256>>>(t & 1, alpha, gamma);
    }
}